// round 4
// baseline (speedup 1.0000x reference)
#include <cuda_runtime.h>

#define BSZ 32
#define CCH 256
#define NPX 4096
#define TC  32
#define TN  32
#define KB  8
#define NT  8            // n-tiles per block
#define CKT (BSZ / KB)   // k-chunks per n-tile = 4
#define CKTOT (NT * CKT) // 32 chunks per block
#define REGF 0.01f

typedef unsigned long long ull;

// packed fp32x2 FMA (Blackwell): 2 FMAs per instruction; ptxas never emits
// this from C++, so inline PTX.
__device__ __forceinline__ void ffma2(ull& acc, ull a, ull b) {
    asm("fma.rn.f32x2 %0, %1, %2, %0;" : "+l"(acc) : "l"(a), "l"(b));
}

__device__ __forceinline__ unsigned smem_u32(const void* p) {
    return (unsigned)__cvta_generic_to_shared(p);
}
__device__ __forceinline__ void cp16(unsigned s, const float* g) {
    asm volatile("cp.async.cg.shared.global [%0], [%1], 16;" :: "r"(s), "l"(g));
}
#define CP_COMMIT() asm volatile("cp.async.commit_group;" ::: "memory")
#define CP_WAIT2()  asm volatile("cp.async.wait_group 2;" ::: "memory")

// ---------------------------------------------------------------------------
// Kernel 1: mean over batch. x: [B, C, N], mean: [C, N]. float4 vectorized.
// ---------------------------------------------------------------------------
__global__ void mvg_mean_kernel(const float* __restrict__ x,
                                float* __restrict__ mean) {
    int idx = blockIdx.x * blockDim.x + threadIdx.x;
    const float4* x4 = (const float4*)x;
    float4 s = make_float4(0.f, 0.f, 0.f, 0.f);
    const int stride = CCH * NPX / 4;
#pragma unroll
    for (int b = 0; b < BSZ; b++) {
        float4 v = x4[b * stride + idx];
        s.x += v.x; s.y += v.y; s.z += v.z; s.w += v.w;
    }
    const float inv = 1.0f / BSZ;
    s.x *= inv; s.y *= inv; s.z *= inv; s.w *= inv;
    ((float4*)mean)[idx] = s;
}

// ---------------------------------------------------------------------------
// Kernel 2: cov[c,d,n] = (sum_b x_c x_d - B*m_c*m_d)/(B-1) + REG*(c==d)
// Block = 32c x 32d tile pair (upper-tri, mirrored writes) x NT=8 n-tiles
// swept with one continuous cp.async pipeline (3 bufs, 2 groups ahead).
// Thread microtile 8c x 8d x 2n, packed f32x2 accumulators, register
// double-buffered smem operands.
// ---------------------------------------------------------------------------
__global__ __launch_bounds__(256, 1)
void mvg_cov_kernel(const float* __restrict__ x,
                    const float* __restrict__ mean,
                    float* __restrict__ cov) {
    // upper-triangular tile pair (ti <= tj) from blockIdx.x in [0,36)
    int rem = blockIdx.x;
    int ti = 0, row = 8;
    while (rem >= row) { rem -= row; row--; ti++; }
    const int tj = ti + rem;
    const bool diag = (ti == tj);
    const int n_base = blockIdx.y * (NT * TN);

    extern __shared__ float sm[];   // 3 bufs x (8192 c + 8192 d) floats

    const int tid = threadIdx.x;
    const int tn  = tid & 15;       // n-pair (covers 2 n)
    const int tcd = tid >> 4;
    const int tc  = tcd & 3;        // 8 c-rows
    const int td  = tcd >> 2;       // 8 d-rows

    // ---- stage global chunk ck ----
    auto stage = [&](int ck) {
        const int t  = ck >> 2;               // n-tile
        const int kb = (ck & 3) * KB;         // batch offset
        const int n0 = n_base + t * TN;
        float* dst = sm + (ck % 3) * 16384;
#pragma unroll
        for (int r = 0; r < 8; r++) {
            int f  = r * 256 + tid;
            int bb = f >> 8;
            int c  = (f >> 3) & 31;
            int nn = (f & 7) << 2;
            unsigned so = smem_u32(dst + (bb * TC + c) * TN + nn);
            cp16(so, &x[((size_t)(kb + bb) * CCH + ti * TC + c) * NPX + n0 + nn]);
            if (!diag)
                cp16(so + 8192 * 4,
                     &x[((size_t)(kb + bb) * CCH + tj * TC + c) * NPX + n0 + nn]);
        }
        CP_COMMIT();
    };

    ull acc[8][8];
#pragma unroll
    for (int i = 0; i < 8; i++)
#pragma unroll
        for (int j = 0; j < 8; j++) acc[i][j] = 0ull;

    // ---- compute one chunk: register-double-buffered inner loop ----
    auto compute = [&](int ck) {
        const float* pc = sm + (ck % 3) * 16384;
        const float* pd = diag ? pc : pc + 8192;
        const float* pa = pc + (tc * 8) * TN + tn * 2;
        const float* pb = pd + (td * 8) * TN + tn * 2;
        ull av[2][8], bv[2][8];
#pragma unroll
        for (int i = 0; i < 8; i++) av[0][i] = *(const ull*)&pa[i * TN];
#pragma unroll
        for (int j = 0; j < 8; j++) bv[0][j] = *(const ull*)&pb[j * TN];
#pragma unroll
        for (int bb = 0; bb < KB; bb++) {
            const int cur = bb & 1, nxt = cur ^ 1;
            if (bb < KB - 1) {
                const float* qa = pa + (bb + 1) * TC * TN;
                const float* qb = pb + (bb + 1) * TC * TN;
#pragma unroll
                for (int i = 0; i < 8; i++) av[nxt][i] = *(const ull*)&qa[i * TN];
#pragma unroll
                for (int j = 0; j < 8; j++) bv[nxt][j] = *(const ull*)&qb[j * TN];
            }
#pragma unroll
            for (int i = 0; i < 8; i++)
#pragma unroll
                for (int j = 0; j < 8; j++)
                    ffma2(acc[i][j], av[cur][i], bv[cur][j]);
        }
    };

    // ---- epilogue for n-tile t: mean correction, scale, write, reset acc ----
    auto epilogue = [&](int t) {
        const float scale = 1.0f / (BSZ - 1);
        const int n = n_base + t * TN + tn * 2;
        float2 mcv[8], mdv[8];
#pragma unroll
        for (int i = 0; i < 8; i++)
            mcv[i] = *(const float2*)&mean[(size_t)(ti * TC + tc * 8 + i) * NPX + n];
#pragma unroll
        for (int j = 0; j < 8; j++)
            mdv[j] = *(const float2*)&mean[(size_t)(tj * TC + td * 8 + j) * NPX + n];
#pragma unroll
        for (int i = 0; i < 8; i++) {
            int c = ti * TC + tc * 8 + i;
#pragma unroll
            for (int j = 0; j < 8; j++) {
                int d = tj * TC + td * 8 + j;
                ull a = acc[i][j];
                float lo = __uint_as_float((unsigned)(a & 0xffffffffull));
                float hi = __uint_as_float((unsigned)(a >> 32));
                lo = (lo - (float)BSZ * mcv[i].x * mdv[j].x) * scale;
                hi = (hi - (float)BSZ * mcv[i].y * mdv[j].y) * scale;
                if (c == d) { lo += REGF; hi += REGF; }
                float2 o = make_float2(lo, hi);
                __stcs((float2*)&cov[((size_t)c * CCH + d) * NPX + n], o);
                if (!diag)
                    __stcs((float2*)&cov[((size_t)d * CCH + c) * NPX + n], o);
                acc[i][j] = 0ull;
            }
        }
    };

    // ---- continuous pipeline over all NT*CKT chunks ----
    stage(0); stage(1); stage(2);
    for (int ck = 0; ck < CKTOT; ck++) {
        CP_WAIT2();            // group ck complete (always exactly ck+3 issued)
        __syncthreads();
        compute(ck);
        __syncthreads();       // all reads of buf ck%3 done
        if (ck + 3 < CKTOT) stage(ck + 3);
        else CP_COMMIT();      // empty group keeps wait_group 2 aligned
        if ((ck & 3) == 3) epilogue(ck >> 2);
    }
}

// ---------------------------------------------------------------------------
extern "C" void kernel_launch(void* const* d_in, const int* in_sizes, int n_in,
                              void* d_out, int out_size) {
    const float* x = (const float*)d_in[0];
    float* out  = (float*)d_out;
    float* mean = out;                          // [C, N]
    float* cov  = out + (size_t)CCH * NPX;      // [C, C, N]

    mvg_mean_kernel<<<(CCH * NPX / 4) / 256, 256>>>(x, mean);

    static bool attr_set = false;
    const int smem_bytes = 3 * 16384 * 4;       // 192 KB
    if (!attr_set) {
        cudaFuncSetAttribute(mvg_cov_kernel,
                             cudaFuncAttributeMaxDynamicSharedMemorySize,
                             smem_bytes);
        attr_set = true;
    }
    dim3 grid(36, NPX / (NT * TN));             // (36, 16)
    mvg_cov_kernel<<<grid, 256, smem_bytes>>>(x, mean, cov);
}